// round 17
// baseline (speedup 1.0000x reference)
#include <cuda_runtime.h>
#include <cuda_fp16.h>
#include <cuda_bf16.h>

#define BB 8
#define TT 4
#define NN 4096
#define EE 65536
#define EF (EE + NN)          // edges + self loops = 69632
#define BN (BB * NN)          // 32768
#define LOG2E 1.44269504f

// ---------------- device scratch ----------------
// hgat in fp16, layout [n][colpair p (32)][batch b (8)] as half2; uint4 = 4 batches
__device__ uint4   g_hgat4[NN * 32 * 2];   // 4 MB
__device__ float   g_est[NN * BB];         // es * log2e, transposed [n*8 + b]
__device__ float   g_edt[NN * BB];         // ed * log2e, transposed [n*8 + b]
__device__ uint4   g_s4[BN * 8];           // GAT output s, fp16 [b*NN+n][64]
__device__ uint4   g_W1h4[80 * 16];        // W1 fp16, rows permuted (s 0..63, x 64..66), 0-pad
__device__ uint4   g_W2h4[80 * 8];         // W2 fp16, permuted + 0-pad
__device__ uint4   g_gWh4[80 * 8];         // gat_W fp16, 0-pad (natural: h 0..63, x 64..66)
__device__ int     g_cnt[NN];
__device__ int     g_cur[NN];
__device__ int     g_off[NN + 1];
__device__ int     g_srcs[EF];

__device__ __forceinline__ float ex2(float x) {
    float r; asm("ex2.approx.f32 %0, %1;" : "=f"(r) : "f"(x)); return r;
}
__device__ __forceinline__ unsigned sptr(const void* p) {
    return (unsigned)__cvta_generic_to_shared(p);
}
__device__ __forceinline__ void ldmA(unsigned addr, unsigned& a0, unsigned& a1,
                                     unsigned& a2, unsigned& a3) {
    asm volatile("ldmatrix.sync.aligned.m8n8.x4.shared.b16 {%0,%1,%2,%3}, [%4];"
        : "=r"(a0), "=r"(a1), "=r"(a2), "=r"(a3) : "r"(addr));
}
__device__ __forceinline__ void ldmBT(unsigned addr, unsigned& b0, unsigned& b1) {
    asm volatile("ldmatrix.sync.aligned.m8n8.x2.trans.shared.b16 {%0,%1}, [%2];"
        : "=r"(b0), "=r"(b1) : "r"(addr));
}
__device__ __forceinline__ void mma16816(float& c0, float& c1, float& c2, float& c3,
    unsigned a0, unsigned a1, unsigned a2, unsigned a3, unsigned b0, unsigned b1) {
    asm volatile("mma.sync.aligned.m16n8k16.row.col.f32.f16.f16.f32 "
        "{%0,%1,%2,%3}, {%4,%5,%6,%7}, {%8,%9}, {%0,%1,%2,%3};"
        : "+f"(c0), "+f"(c1), "+f"(c2), "+f"(c3)
        : "r"(a0), "r"(a1), "r"(a2), "r"(a3), "r"(b0), "r"(b1));
}

// ---------------- kernel 1: edge count + GAT step-0 + weight conversion ---------
// blocks [0,4096): gat0 ; [4096,4368): count ; [4368,4408): wconv (2 rows/block)
__global__ __launch_bounds__(256) void gat0_count_kernel(
    const float* __restrict__ x, const float* __restrict__ gat_W,
    const float* __restrict__ a_src, const float* __restrict__ a_dst,
    const int* __restrict__ dst,
    const float* __restrict__ W1, const float* __restrict__ W2)
{
    if (blockIdx.x >= 4368) {
        // weight fp16 conversion: W1h/W2h rows 0..63 = s-block (orig 3..66),
        // 64..66 = x-block (orig 0..2), 67..79 zero. gWh natural order.
        int r = (blockIdx.x - 4368) * 2 + (threadIdx.x >> 7);
        int c = threadIdx.x & 127;
        __half* W1h = (__half*)g_W1h4;
        __half* W2h = (__half*)g_W2h4;
        __half* gWh = (__half*)g_gWh4;
        float v = 0.f;
        if (r < 64)      v = W1[(3 + r) * 128 + c];
        else if (r < 67) v = W1[(r - 64) * 128 + c];
        W1h[r * 128 + c] = __float2half(v);
        if (c < 64) {
            float v2 = 0.f, v3 = 0.f;
            if (r < 64)      v2 = W2[(3 + r) * 64 + c];
            else if (r < 67) v2 = W2[(r - 64) * 64 + c];
            if (r < 67)      v3 = gat_W[r * 64 + c];
            W2h[r * 64 + c] = __float2half(v2);
            gWh[r * 64 + c] = __float2half(v3);
        }
        return;
    }
    if (blockIdx.x >= 4096) {
        int i = (blockIdx.x - 4096) * 256 + threadIdx.x;
        if (i < EF) {
            int d = (i < EE) ? dst[i] : (i - EE);
            atomicAdd(&g_cnt[d], 1);
        }
        return;
    }
    int w = threadIdx.x >> 5, lane = threadIdx.x & 31;
    int nid = blockIdx.x * 8 + w;
    int b = nid >> 12, n = nid & 4095;
    const float* xp = &x[((b * TT + 0) * NN + n) * 3];
    float x0 = __ldg(xp), x1 = __ldg(xp + 1), x2 = __ldg(xp + 2);
    int c0 = 2 * lane, c1 = 2 * lane + 1;
    float h0 = x0 * __ldg(&gat_W[64 * 64 + c0]) + x1 * __ldg(&gat_W[65 * 64 + c0])
             + x2 * __ldg(&gat_W[66 * 64 + c0]);
    float h1 = x0 * __ldg(&gat_W[64 * 64 + c1]) + x1 * __ldg(&gat_W[65 * 64 + c1])
             + x2 * __ldg(&gat_W[66 * 64 + c1]);
    ((__half2*)g_hgat4)[(n * 32 + lane) * 8 + b] = __floats2half2_rn(h0, h1);
    float es = h0 * __ldg(&a_src[c0]) + h1 * __ldg(&a_src[c1]);
    float ed = h0 * __ldg(&a_dst[c0]) + h1 * __ldg(&a_dst[c1]);
    #pragma unroll
    for (int o = 16; o > 0; o >>= 1) {
        es += __shfl_down_sync(0xFFFFFFFFu, es, o);
        ed += __shfl_down_sync(0xFFFFFFFFu, ed, o);
    }
    if (lane == 0) { g_est[n * 8 + b] = es * LOG2E; g_edt[n * 8 + b] = ed * LOG2E; }
}

// ---------------- kernel 2: prefix scan (+ re-zero counters for graph replay) ----
__global__ void scan_kernel() {
    __shared__ int tsum[1024];
    int tid = threadIdx.x;
    int base = tid * 4;
    int c0 = g_cnt[base + 0], c1 = g_cnt[base + 1];
    int c2 = g_cnt[base + 2], c3 = g_cnt[base + 3];
    int sum4 = c0 + c1 + c2 + c3;
    tsum[tid] = sum4;
    __syncthreads();
    for (int ofs = 1; ofs < 1024; ofs <<= 1) {
        int add = 0;
        if (tid >= ofs) add = tsum[tid - ofs];
        __syncthreads();
        tsum[tid] += add;
        __syncthreads();
    }
    int excl = tsum[tid] - sum4;
    g_off[base + 0] = excl;
    g_off[base + 1] = excl + c0;
    g_off[base + 2] = excl + c0 + c1;
    g_off[base + 3] = excl + c0 + c1 + c2;
    if (tid == 1023) g_off[NN] = tsum[1023];
    g_cnt[base + 0] = 0; g_cnt[base + 1] = 0; g_cnt[base + 2] = 0; g_cnt[base + 3] = 0;
    g_cur[base + 0] = 0; g_cur[base + 1] = 0; g_cur[base + 2] = 0; g_cur[base + 3] = 0;
}

// ---------------- kernel 3: CSR scatter ----------------
__global__ void scatter_kernel(const int* __restrict__ src, const int* __restrict__ dst) {
    int i = blockIdx.x * blockDim.x + threadIdx.x;
    if (i >= EF) return;
    int s, d;
    if (i < EE) { s = src[i]; d = dst[i]; }
    else        { s = i - EE; d = i - EE; }
    int pos = g_off[d] + atomicAdd(&g_cur[d], 1);
    g_srcs[pos] = s;
}

// ---------------- kernel 4: gather, 4 batches/warp, depth-2 pipeline -------------
__global__ __launch_bounds__(256) void gat_gather_kernel(const float* __restrict__ gat_b)
{
    int gw = blockIdx.x * 8 + (threadIdx.x >> 5);    // 0..8191
    int n = gw >> 1, bg = (gw & 1) * 4, bq = gw & 1;
    int lane = threadIdx.x & 31;

    float4 ed4 = *(const float4*)&g_edt[n * 8 + bg];
    float edv[4] = {ed4.x, ed4.y, ed4.z, ed4.w};
    float S[4], a0[4], a1[4];
    #pragma unroll
    for (int b = 0; b < 4; b++) { S[b] = 0.0f; a0[b] = 0.0f; a1[b] = 0.0f; }

    int e0 = g_off[n];
    int en1 = g_off[n + 1] - 1;
    int cnt = en1 - e0 + 1;
    int hofs = lane * 2 + bq;

    int sA = __ldg(&g_srcs[e0]);
    int s1 = __ldg(&g_srcs[min(e0 + 1, en1)]);
    int sC = __ldg(&g_srcs[min(e0 + 2, en1)]);
    int sD = __ldg(&g_srcs[min(e0 + 3, en1)]);
    float4 esv[2]; uint4 hv[2];
    esv[0] = *(const float4*)&g_est[sA * 8 + bg];
    hv[0]  = __ldg(&g_hgat4[sA * 64 + hofs]);
    esv[1] = *(const float4*)&g_est[s1 * 8 + bg];
    hv[1]  = __ldg(&g_hgat4[s1 * 64 + hofs]);

    #pragma unroll 2
    for (int i = 0; i < cnt; i++) {
        int cur = i & 1;
        float4 ces = esv[cur];
        uint4  ch  = hv[cur];
        esv[cur] = *(const float4*)&g_est[sC * 8 + bg];
        hv[cur]  = __ldg(&g_hgat4[sC * 64 + hofs]);
        sC = sD;
        sD = __ldg(&g_srcs[min(e0 + i + 4, en1)]);

        float esvv[4] = {ces.x, ces.y, ces.z, ces.w};
        unsigned hw[4] = {ch.x, ch.y, ch.z, ch.w};
        #pragma unroll
        for (int b = 0; b < 4; b++) {
            float ev = esvv[b] + edv[b];
            ev = fmaxf(ev, 0.2f * ev);
            float w = ex2(ev);
            float2 f = __half22float2(*(__half2*)&hw[b]);
            S[b] += w; a0[b] += w * f.x; a1[b] += w * f.y;
        }
    }
    float gb0 = __ldg(&gat_b[2 * lane]), gb1 = __ldg(&gat_b[2 * lane + 1]);
    #pragma unroll
    for (int b = 0; b < 4; b++) {
        float inv = 1.0f / S[b];
        ((__half2*)g_s4)[((bg + b) * NN + n) * 32 + lane] =
            __floats2half2_rn(a0[b] * inv + gb0, a1[b] * inv + gb1);
    }
}

// ---------------- kernel 5: GRU cell + fused GAT node transform (MMA fp16) -------
// 256 threads = 8 warps, 64 nodes/block, dynamic smem.
// A layout (s-first): s/rs at k 0..63, x at 64..66, 0-pad 67..79.
// phase1: [64x80] @ W1h[80x128]; phase2: [64x80] @ W2h[80x64];
// phase3 (t<3): hgat = [h, x(t+1)] @ gWh; es/ed staged smem reduce.
// last step: output projection instead of phase3.
// smem layout (bytes): sz 0, szrs 11264, sW 22528, su 44288,
//                      sb1 60672, sb2 61184, sa 61440, sow 61952, sob 62720
#define GRU_SMEM 62752
extern __shared__ char dynsm[];
__global__ __launch_bounds__(256) void gru_kernel(
    const float* __restrict__ x,
    const float* __restrict__ b1, const float* __restrict__ b2,
    const float* __restrict__ a_src, const float* __restrict__ a_dst,
    const float* __restrict__ oW, const float* __restrict__ ob,
    float* __restrict__ out, int t, int last)
{
    __half* sz   = (__half*)(dynsm);           // [64][88]
    __half* szrs = (__half*)(dynsm + 11264);   // [64][88]
    __half* sW   = (__half*)(dynsm + 22528);   // [80][136]
    float*  su   = (float*)(dynsm + 44288);    // [64][64]
    float*  sb1  = (float*)(dynsm + 60672);
    float*  sb2  = (float*)(dynsm + 61184);
    float*  sa   = (float*)(dynsm + 61440);
    float*  sow  = (float*)(dynsm + 61952);
    float*  sob  = (float*)(dynsm + 62720);
    float*  sPES = su;                          // [64 nodes][32 slots]
    float*  sPED = su + 2048;

    int tid = threadIdx.x;
    int lane = tid & 31;
    int w = tid >> 5;
    int nbase = blockIdx.x * 64;

    // W1h -> smem (uint4 copy, 80x16)
    for (int i = tid; i < 1280; i += 256) {
        int k = i >> 4, q = i & 15;
        *(uint4*)&sW[k * 136 + q * 8] = g_W1h4[i];
    }
    if (tid < 128) sb1[tid] = b1[tid];
    if (tid < 64)  sb2[tid] = b2[tid];
    if (last) {
        if (tid < 192) sow[tid] = oW[tid];
        if (tid < 3)   sob[tid] = ob[tid];
    }

    // s (fp16) -> sz[.][0..63] (uint4 copy, 64x8)
    for (int i = tid; i < 512; i += 256) {
        int ln = i >> 3, q = i & 7;
        *(uint4*)&sz[ln * 88 + q * 8] = g_s4[(nbase + ln) * 8 + q];
    }
    // zero pads k=67..79 in both A buffers
    for (int i = tid; i < 64 * 13; i += 256) {
        int ln = i / 13, k = 67 + (i % 13);
        sz[ln * 88 + k]   = __float2half(0.f);
        szrs[ln * 88 + k] = __float2half(0.f);
    }
    // x -> k 64..66 in both A buffers
    if (tid < 192) {
        int ln = tid / 3, f = tid % 3;
        int nid = nbase + ln;
        int b = nid >> 12, n = nid & 4095;
        __half hx = __float2half(x[((b * TT + t) * NN + n) * 3 + f]);
        sz[ln * 88 + 64 + f]   = hx;
        szrs[ln * 88 + 64 + f] = hx;
    }
    __syncthreads();

    // ---- phase 1 MMA: ru ----   M=64 (4 m-tiles), N: warp w -> cols w*16..+15
    int nb = w * 16;
    float acc[4][2][4];
    #pragma unroll
    for (int m = 0; m < 4; m++)
        #pragma unroll
        for (int nt = 0; nt < 2; nt++) {
            int j0 = nb + nt * 8 + 2 * (lane & 3);
            acc[m][nt][0] = sb1[j0];     acc[m][nt][1] = sb1[j0 + 1];
            acc[m][nt][2] = sb1[j0];     acc[m][nt][3] = sb1[j0 + 1];
        }
    #pragma unroll
    for (int kb = 0; kb < 5; kb++) {
        unsigned a[4][4];
        #pragma unroll
        for (int m = 0; m < 4; m++)
            ldmA(sptr(&sz[(m * 16 + (lane & 15)) * 88 + kb * 16 + (lane >> 4) * 8]),
                 a[m][0], a[m][1], a[m][2], a[m][3]);
        #pragma unroll
        for (int nt = 0; nt < 2; nt++) {
            unsigned b0, b1v;
            ldmBT(sptr(&sW[(kb * 16 + (lane & 15)) * 136 + nb + nt * 8]), b0, b1v);
            #pragma unroll
            for (int m = 0; m < 4; m++)
                mma16816(acc[m][nt][0], acc[m][nt][1], acc[m][nt][2], acc[m][nt][3],
                         a[m][0], a[m][1], a[m][2], a[m][3], b0, b1v);
        }
    }

    // epilogue 1: sigmoid -> r*s (cols<64) / u (cols>=64)
    #pragma unroll
    for (int m = 0; m < 4; m++)
        #pragma unroll
        for (int nt = 0; nt < 2; nt++) {
            int j0 = nb + nt * 8 + 2 * (lane & 3);
            #pragma unroll
            for (int rr = 0; rr < 2; rr++) {
                int node = m * 16 + (lane >> 2) + rr * 8;
                float s0 = 1.f / (1.f + __expf(-acc[m][nt][rr * 2 + 0]));
                float s1 = 1.f / (1.f + __expf(-acc[m][nt][rr * 2 + 1]));
                if (j0 < 64) {
                    szrs[node * 88 + j0]     = __float2half(s0 * __half2float(sz[node * 88 + j0]));
                    szrs[node * 88 + j0 + 1] = __float2half(s1 * __half2float(sz[node * 88 + j0 + 1]));
                } else {
                    su[node * 64 + j0 - 64] = s0;
                    su[node * 64 + j0 - 63] = s1;
                }
            }
        }
    __syncthreads();   // all W1 reads + szrs/su writes complete

    // W2h -> smem (uint4 copy, 80x8)
    for (int i = tid; i < 640; i += 256) {
        int k = i >> 3, q = i & 7;
        *(uint4*)&sW[k * 136 + q * 8] = g_W2h4[i];
    }
    __syncthreads();

    // ---- phase 2 MMA: c ----   N: warp w -> cols w*8..+7
    int nb2 = w * 8;
    float a2c[4][4];
    {
        int j0 = nb2 + 2 * (lane & 3);
        #pragma unroll
        for (int m = 0; m < 4; m++) {
            a2c[m][0] = sb2[j0];     a2c[m][1] = sb2[j0 + 1];
            a2c[m][2] = sb2[j0];     a2c[m][3] = sb2[j0 + 1];
        }
    }
    #pragma unroll
    for (int kb = 0; kb < 5; kb++) {
        unsigned b0, b1v;
        ldmBT(sptr(&sW[(kb * 16 + (lane & 15)) * 136 + nb2]), b0, b1v);
        #pragma unroll
        for (int m = 0; m < 4; m++) {
            unsigned a[4];
            ldmA(sptr(&szrs[(m * 16 + (lane & 15)) * 88 + kb * 16 + (lane >> 4) * 8]),
                 a[0], a[1], a[2], a[3]);
            mma16816(a2c[m][0], a2c[m][1], a2c[m][2], a2c[m][3],
                     a[0], a[1], a[2], a[3], b0, b1v);
        }
    }

    // epilogue 2: c = tanh, h = u*s + (1-u)*c  (h kept in registers)
    int j0b = nb2 + 2 * (lane & 3);
    float hreg[4][2][2];
    #pragma unroll
    for (int m = 0; m < 4; m++)
        #pragma unroll
        for (int rr = 0; rr < 2; rr++) {
            int node = m * 16 + (lane >> 2) + rr * 8;
            float cc0 = tanhf(a2c[m][rr * 2 + 0]);
            float cc1 = tanhf(a2c[m][rr * 2 + 1]);
            float u0 = su[node * 64 + j0b], u1 = su[node * 64 + j0b + 1];
            float s0 = __half2float(sz[node * 88 + j0b]);
            float s1 = __half2float(sz[node * 88 + j0b + 1]);
            hreg[m][rr][0] = u0 * s0 + (1.f - u0) * cc0;
            hreg[m][rr][1] = u1 * s1 + (1.f - u1) * cc1;
        }
    __syncthreads();   // szrs/su/sW(W2) reads all complete

    if (!last) {
        // ---- phase 3: hgat = [h, x(t+1)] @ gat_W ----
        #pragma unroll
        for (int m = 0; m < 4; m++)
            #pragma unroll
            for (int rr = 0; rr < 2; rr++) {
                int node = m * 16 + (lane >> 2) + rr * 8;
                *(__half2*)&szrs[node * 88 + j0b] =
                    __floats2half2_rn(hreg[m][rr][0], hreg[m][rr][1]);
            }
        if (tid < 192) {
            int ln = tid / 3, f = tid % 3;
            int nid = nbase + ln;
            int b = nid >> 12, n = nid & 4095;
            szrs[ln * 88 + 64 + f] = __float2half(x[((b * TT + t + 1) * NN + n) * 3 + f]);
        }
        // gWh -> smem (uint4 copy, 80x8; includes zero rows)
        for (int i = tid; i < 640; i += 256) {
            int k = i >> 3, q = i & 7;
            *(uint4*)&sW[k * 136 + q * 8] = g_gWh4[i];
        }
        if (tid < 128) sa[tid] = (tid < 64) ? a_src[tid] : a_dst[tid - 64];
        __syncthreads();

        float gc[4][4];
        #pragma unroll
        for (int m = 0; m < 4; m++)
            #pragma unroll
            for (int c = 0; c < 4; c++) gc[m][c] = 0.f;
        #pragma unroll
        for (int kb = 0; kb < 5; kb++) {
            unsigned b0, b1v;
            ldmBT(sptr(&sW[(kb * 16 + (lane & 15)) * 136 + nb2]), b0, b1v);
            #pragma unroll
            for (int m = 0; m < 4; m++) {
                unsigned a[4];
                ldmA(sptr(&szrs[(m * 16 + (lane & 15)) * 88 + kb * 16 + (lane >> 4) * 8]),
                     a[0], a[1], a[2], a[3]);
                mma16816(gc[m][0], gc[m][1], gc[m][2], gc[m][3],
                         a[0], a[1], a[2], a[3], b0, b1v);
            }
        }
        // store hgat (half2 pair = fragment cols) + staged es/ed partials
        int slot = w * 4 + (lane & 3);
        int p = (nb2 >> 1) + (lane & 3);
        #pragma unroll
        for (int m = 0; m < 4; m++)
            #pragma unroll
            for (int rr = 0; rr < 2; rr++) {
                int node = m * 16 + (lane >> 2) + rr * 8;
                int nid = nbase + node;
                int b = nid >> 12, n = nid & 4095;
                float h0 = gc[m][rr * 2 + 0], h1 = gc[m][rr * 2 + 1];
                ((__half2*)g_hgat4)[(n * 32 + p) * 8 + b] = __floats2half2_rn(h0, h1);
                sPES[node * 32 + slot] = h0 * sa[j0b] + h1 * sa[j0b + 1];
                sPED[node * 32 + slot] = h0 * sa[64 + j0b] + h1 * sa[64 + j0b + 1];
            }
        __syncthreads();
        if (tid < 64) {
            float es = 0.f, ed = 0.f;
            #pragma unroll 8
            for (int s = 0; s < 32; s++) {
                es += sPES[tid * 32 + s];
                ed += sPED[tid * 32 + s];
            }
            int nid = nbase + tid;
            int b = nid >> 12, n = nid & 4095;
            g_est[n * 8 + b] = es * LOG2E;
            g_edt[n * 8 + b] = ed * LOG2E;
        }
    } else {
        // output projection: h -> su, then out = h @ out_W + out_b
        #pragma unroll
        for (int m = 0; m < 4; m++)
            #pragma unroll
            for (int rr = 0; rr < 2; rr++) {
                int node = m * 16 + (lane >> 2) + rr * 8;
                su[node * 64 + j0b]     = hreg[m][rr][0];
                su[node * 64 + j0b + 1] = hreg[m][rr][1];
            }
        __syncthreads();
        if (tid < 192) {
            int ln = tid / 3, d = tid % 3;
            float acc3 = sob[d];
            #pragma unroll 8
            for (int k = 0; k < 64; k++) acc3 += su[ln * 64 + k] * sow[k * 3 + d];
            out[(nbase + ln) * 3 + d] = acc3;
        }
    }
}

// ---------------- launch ----------------
extern "C" void kernel_launch(void* const* d_in, const int* in_sizes, int n_in,
                              void* d_out, int out_size)
{
    const float* x       = (const float*)d_in[0];
    const int*   src     = (const int*)  d_in[1];
    const int*   dst     = (const int*)  d_in[2];
    const float* gat_W   = (const float*)d_in[3];
    const float* a_src   = (const float*)d_in[4];
    const float* a_dst   = (const float*)d_in[5];
    const float* gat_b   = (const float*)d_in[6];
    const float* gru1_W  = (const float*)d_in[7];
    const float* gru1_b  = (const float*)d_in[8];
    const float* gru2_W  = (const float*)d_in[9];
    const float* gru2_b  = (const float*)d_in[10];
    const float* out_W   = (const float*)d_in[11];
    const float* out_b   = (const float*)d_in[12];
    float* out = (float*)d_out;

    cudaFuncSetAttribute(gru_kernel,
                         cudaFuncAttributeMaxDynamicSharedMemorySize, 65536);

    gat0_count_kernel<<<4096 + 272 + 40, 256>>>(x, gat_W, a_src, a_dst, dst,
                                                gru1_W, gru2_W);
    scan_kernel<<<1, 1024>>>();
    scatter_kernel<<<(EF + 255) / 256, 256>>>(src, dst);

    for (int t = 0; t < TT; t++) {
        gat_gather_kernel<<<NN / 4, 256>>>(gat_b);
        gru_kernel<<<BN / 64, 256, GRU_SMEM>>>(x, gru1_b, gru2_b, a_src, a_dst,
                                               out_W, out_b, out, t,
                                               (t == TT - 1) ? 1 : 0);
    }
}